// round 1
// baseline (speedup 1.0000x reference)
#include <cuda_runtime.h>
#include <math.h>

#define TN 200
#define BN 256
#define EN 300
#define HN 512
#define GN 1536            // 3*H
#define MN (TN*BN)         // 51200

// ---------------- static device scratch (no dynamic allocation allowed) ----------------
__device__ float g_xproj[(size_t)2 * TN * BN * GN];   // [dir][t][b][3H]  (~629 MB)
__device__ float g_out  [(size_t)2 * TN * BN * HN];   // [dir][t][b][H]   (~210 MB)
__device__ float g_h    [2 * 2 * BN * HN];            // [dir][pingpong][b][H]
__device__ float g_v    [2 * HN];                     // collapsed attention vector
__device__ float g_cbias;                             // collapsed attention bias
__device__ int   g_inv  [BN];                         // inverse of sorted_idx
__device__ float g_logits[BN * TN];
__device__ float g_att   [BN * TN];

// ---------------- init: zero hidden-state ping-pong buffers (every launch) -------------
__global__ void init_kernel() {
    int i = blockIdx.x * blockDim.x + threadIdx.x;
    if (i < 2 * 2 * BN * HN) g_h[i] = 0.0f;
}

// ---------------- prep: v = W_comb @ W_attn,  c = W_comb . b_attn,  inv perm ----------
__global__ void prep_kernel(const float* __restrict__ Wattn,
                            const float* __restrict__ battn,
                            const float* __restrict__ Wcomb,
                            const int*   __restrict__ sidx) {
    int tid = threadIdx.x;   // 1024 threads
    float s = 0.0f;
    for (int m = 0; m < 2 * HN; m++)
        s += Wcomb[m] * Wattn[(size_t)m * (2 * HN) + tid];
    g_v[tid] = s;
    if (tid == 0) {
        float c = 0.0f;
        for (int m = 0; m < 2 * HN; m++) c += Wcomb[m] * battn[m];
        g_cbias = c;
    }
    if (tid < BN) g_inv[sidx[tid]] = tid;
}

// ---------------- input projection GEMM: xproj = inp @ W_ih^T + b_ih -------------------
// C[m][g] = sum_e A[m][e] * W[g][e],  M=51200, N=1536, K=300.  128x128 tile, 8x8/thread.
__global__ __launch_bounds__(256) void proj_kernel(const float* __restrict__ inp,
                                                   const float* __restrict__ Wf,
                                                   const float* __restrict__ bf,
                                                   const float* __restrict__ Wb,
                                                   const float* __restrict__ bb) {
    __shared__ float As[8][128];
    __shared__ float Ws[8][128];

    int dir = blockIdx.z;
    const float* W    = dir ? Wb : Wf;
    const float* bias = dir ? bb : bf;
    int m0 = blockIdx.x * 128;
    int g0 = blockIdx.y * 128;
    int tid = threadIdx.x;
    int tx = tid & 15, ty = tid >> 4;
    int lr = tid >> 1, lk = (tid & 1) * 4;

    float acc[8][8];
#pragma unroll
    for (int i = 0; i < 8; i++)
#pragma unroll
        for (int j = 0; j < 8; j++) acc[i][j] = 0.0f;

    const float* Arow = inp + (size_t)(m0 + lr) * EN;
    const float* Wrow = W   + (size_t)(g0 + lr) * EN;

    for (int k0 = 0; k0 < EN; k0 += 8) {
#pragma unroll
        for (int u = 0; u < 4; u++) {
            int k = k0 + lk + u;
            As[lk + u][lr] = (k < EN) ? Arow[k] : 0.0f;
            Ws[lk + u][lr] = (k < EN) ? Wrow[k] : 0.0f;
        }
        __syncthreads();
#pragma unroll
        for (int kk = 0; kk < 8; kk++) {
            float4 a0 = *(const float4*)&As[kk][ty * 8];
            float4 a1 = *(const float4*)&As[kk][ty * 8 + 4];
            float4 b0 = *(const float4*)&Ws[kk][tx * 8];
            float4 b1 = *(const float4*)&Ws[kk][tx * 8 + 4];
            float av[8] = {a0.x, a0.y, a0.z, a0.w, a1.x, a1.y, a1.z, a1.w};
            float bv[8] = {b0.x, b0.y, b0.z, b0.w, b1.x, b1.y, b1.z, b1.w};
#pragma unroll
            for (int i = 0; i < 8; i++)
#pragma unroll
                for (int j = 0; j < 8; j++) acc[i][j] += av[i] * bv[j];
        }
        __syncthreads();
    }

#pragma unroll
    for (int i = 0; i < 8; i++) {
        int m = m0 + ty * 8 + i;
        float* outp = g_xproj + ((size_t)dir * MN + m) * GN + g0 + tx * 8;
#pragma unroll
        for (int j = 0; j < 8; j++) outp[j] = acc[i][j] + bias[g0 + tx * 8 + j];
    }
}

// ---------------- one GRU time step (both directions), fused GEMM + pointwise ----------
// Block tile: 32 batch rows x 32 h-cols x 3 gates.  hgates = h_prev @ W_hh^T + b_hh.
__global__ __launch_bounds__(256) void step_kernel(const float* __restrict__ Whf,
                                                   const float* __restrict__ bhf,
                                                   const float* __restrict__ Whb,
                                                   const float* __restrict__ bhb,
                                                   const int*   __restrict__ slen,
                                                   int t) {
    __shared__ float hs[32][33];        // [b_local][kk]
    __shared__ float ws[3][32][33];     // [gate][kk][c]

    int dir = blockIdx.z;
    int tt  = dir ? (TN - 1 - t) : t;
    const float* W  = dir ? Whb : Whf;
    const float* bh = dir ? bhb : bhf;
    int j0 = blockIdx.x * 32;
    int b0 = blockIdx.y * 32;
    int tid = threadIdx.x;
    int c = tid & 31, rgrp = tid >> 5;
    int pp = t & 1;

    const float* hsrc = g_h + (size_t)(dir * 2 + pp)       * BN * HN;
    float*       hdst = g_h + (size_t)(dir * 2 + (pp ^ 1)) * BN * HN;

    float acc0[4] = {0, 0, 0, 0}, acc1[4] = {0, 0, 0, 0}, acc2[4] = {0, 0, 0, 0};

    int lb = tid >> 3, lk = (tid & 7) * 4;

    for (int k0 = 0; k0 < HN; k0 += 32) {
        float4 hv = *(const float4*)&hsrc[(size_t)(b0 + lb) * HN + k0 + lk];
        hs[lb][lk + 0] = hv.x; hs[lb][lk + 1] = hv.y;
        hs[lb][lk + 2] = hv.z; hs[lb][lk + 3] = hv.w;
#pragma unroll
        for (int p = 0; p < 3; p++) {
            int v   = tid + 256 * p;
            int kk4 = v & 7;
            int cc  = (v >> 3) & 31;
            int g   = v >> 8;
            float4 wv = *(const float4*)&W[(size_t)(g * HN + j0 + cc) * HN + k0 + kk4 * 4];
            ws[g][kk4 * 4 + 0][cc] = wv.x; ws[g][kk4 * 4 + 1][cc] = wv.y;
            ws[g][kk4 * 4 + 2][cc] = wv.z; ws[g][kk4 * 4 + 3][cc] = wv.w;
        }
        __syncthreads();
#pragma unroll
        for (int kk = 0; kk < 32; kk++) {
            float w0 = ws[0][kk][c], w1 = ws[1][kk][c], w2 = ws[2][kk][c];
#pragma unroll
            for (int i = 0; i < 4; i++) {
                float h = hs[rgrp * 4 + i][kk];
                acc0[i] += h * w0;
                acc1[i] += h * w1;
                acc2[i] += h * w2;
            }
        }
        __syncthreads();
    }

    int j = j0 + c;
    float br = bh[j], bz = bh[HN + j], bn = bh[2 * HN + j];

#pragma unroll
    for (int i = 0; i < 4; i++) {
        int row = b0 + rgrp * 4 + i;
        const float* xp = g_xproj + ((size_t)dir * MN + (size_t)tt * BN + row) * GN;
        float r = 1.0f / (1.0f + expf(-(xp[j]          + acc0[i] + br)));
        float z = 1.0f / (1.0f + expf(-(xp[HN + j]     + acc1[i] + bz)));
        float n = tanhf(xp[2 * HN + j] + r * (acc2[i] + bn));
        float hold = hsrc[(size_t)row * HN + j];
        float hnew = (1.0f - z) * n + z * hold;
        bool m = tt < slen[row];
        hdst[(size_t)row * HN + j] = m ? hnew : hold;
        g_out[(((size_t)dir * TN + tt) * BN + row) * HN + j] = m ? hnew : 0.0f;
    }
}

// ---------------- logits[ob][t] = unpacked . v + c  (dot of length 1024) ---------------
__global__ void logits_kernel(const int* __restrict__ sidx) {
    int j = blockIdx.x;       // sorted batch index
    int t = blockIdx.y;
    int tid = threadIdx.x;    // 128 threads

    const float* of = g_out + (((size_t)0 * TN + t) * BN + j) * HN;
    const float* ob = g_out + (((size_t)1 * TN + t) * BN + j) * HN;
    float s = 0.0f;
    for (int h = tid; h < HN; h += 128)
        s += of[h] * g_v[h] + ob[h] * g_v[HN + h];

    // warp + block reduce (128 threads = 4 warps)
    for (int o = 16; o > 0; o >>= 1) s += __shfl_down_sync(0xffffffff, s, o);
    __shared__ float red[4];
    if ((tid & 31) == 0) red[tid >> 5] = s;
    __syncthreads();
    if (tid == 0) {
        float tot = red[0] + red[1] + red[2] + red[3] + g_cbias;
        g_logits[(size_t)sidx[j] * TN + t] = tot;
    }
}

// ---------------- masked softmax over t per (original) batch ---------------------------
__global__ void softmax_kernel(const int* __restrict__ seqlen) {
    int b = blockIdx.x;
    int tid = threadIdx.x;    // 256 threads, T=200 active
    int len = seqlen[b];
    bool valid = (tid < TN) && (tid < len);
    float l = valid ? g_logits[(size_t)b * TN + tid] : -1e30f;

    __shared__ float sm[256];
    sm[tid] = l;
    __syncthreads();
    for (int s = 128; s > 0; s >>= 1) {
        if (tid < s) sm[tid] = fmaxf(sm[tid], sm[tid + s]);
        __syncthreads();
    }
    float mx = sm[0];
    __syncthreads();
    float e = valid ? expf(l - mx) : 0.0f;
    sm[tid] = e;
    __syncthreads();
    for (int s = 128; s > 0; s >>= 1) {
        if (tid < s) sm[tid] += sm[tid + s];
        __syncthreads();
    }
    float inv = 1.0f / sm[0];
    if (tid < TN) g_att[(size_t)b * TN + tid] = e * inv;
}

// ---------------- weighted sum: sent[ob][h] = sum_t a[ob][t] * unpacked[ob][t][h] ------
__global__ void wsum_kernel(float* __restrict__ out) {
    int ob  = blockIdx.x;
    int h   = blockIdx.y * 256 + threadIdx.x;   // 0..1023
    int j   = g_inv[ob];
    int d   = (h < HN) ? 0 : 1;
    int hh  = (h < HN) ? h : (h - HN);

    const float* av   = g_att + (size_t)ob * TN;
    const float* base = g_out + ((size_t)d * TN * BN + j) * HN + hh;

    float acc = 0.0f;
    for (int t = 0; t < TN; t++)
        acc += av[t] * base[(size_t)t * BN * HN];
    out[(size_t)ob * (2 * HN) + h] = acc;
}

// ---------------- launch ----------------------------------------------------------------
extern "C" void kernel_launch(void* const* d_in, const int* in_sizes, int n_in,
                              void* d_out, int out_size) {
    const float* inp    = (const float*)d_in[0];
    const float* Wih_f  = (const float*)d_in[1];
    const float* Whh_f  = (const float*)d_in[2];
    const float* bih_f  = (const float*)d_in[3];
    const float* bhh_f  = (const float*)d_in[4];
    const float* Wih_b  = (const float*)d_in[5];
    const float* Whh_b  = (const float*)d_in[6];
    const float* bih_b  = (const float*)d_in[7];
    const float* bhh_b  = (const float*)d_in[8];
    const float* Wattn  = (const float*)d_in[9];
    const float* battn  = (const float*)d_in[10];
    const float* Wcomb  = (const float*)d_in[11];
    const int*   slen_s = (const int*)d_in[12];   // sorted_seq_length
    const int*   sidx   = (const int*)d_in[13];   // sorted_idx
    const int*   seqlen = (const int*)d_in[14];   // seq_length_tensor
    float* out = (float*)d_out;

    init_kernel<<<(2 * 2 * BN * HN + 255) / 256, 256>>>();
    prep_kernel<<<1, 1024>>>(Wattn, battn, Wcomb, sidx);
    proj_kernel<<<dim3(MN / 128, GN / 128, 2), 256>>>(inp, Wih_f, bih_f, Wih_b, bih_b);
    for (int t = 0; t < TN; t++)
        step_kernel<<<dim3(HN / 32, BN / 32, 2), 256>>>(Whh_f, bhh_f, Whh_b, bhh_b, slen_s, t);
    logits_kernel<<<dim3(BN, TN), 128>>>(sidx);
    softmax_kernel<<<BN, 256>>>(seqlen);
    wsum_kernel<<<dim3(BN, 4), 256>>>(out);
}